// round 6
// baseline (speedup 1.0000x reference)
#include <cuda_runtime.h>
#include <cuda_fp16.h>

#define D 64
#define ALPHA 0.2f
#define MAX_N 131072
#define CAP 48   // ELL capacity: deg ~ 1+Poisson(16); 48 is ~7.8 sigma out

// Static scratch (BSS zero-init; k_aggregate re-zeroes g_cnt every run so
// graph replays always see a clean histogram).
// ELL footprint: MAX_N*CAP*8B = 50MB static; live set 100k*48*8 = 38.4MB
// -> L2-resident together with g_xh (12.8MB).
__device__ int     g_cnt[MAX_N];
__device__ float2  g_s1[MAX_N];       // per-node source-side scores (h0,h1)
__device__ float2  g_s2[MAX_N];       // per-node dest-side scores (h0,h1)
__device__ __half2 g_xh[MAX_N * 32];  // fp16 copy of x, 2 feats per lane
__device__ __align__(16) unsigned long long g_ell[MAX_N * CAP]; // (col<<32)|half2(w0,w1)

// One warp per node: per-head scores + fp16 conversion of x (x read once).
// W/a staged as fused per-feature vectors in shared memory.
__global__ void k_precompute(const float* __restrict__ x,
                             const float* __restrict__ W,
                             const float* __restrict__ a, int n) {
    __shared__ float v00[64], v01[64], v10[64], v11[64]; // W[h][j]*a[h][..j]
    int t = threadIdx.x;
    if (t < 64) {
        float w0 = W[t], w1 = W[64 + t];
        v00[t] = w0 * a[t];
        v01[t] = w0 * a[64 + t];
        v10[t] = w1 * a[128 + t];
        v11[t] = w1 * a[192 + t];
    }
    __syncthreads();
    int warp = (blockIdx.x * blockDim.x + t) >> 5;
    int lane = t & 31;
    if (warp >= n) return;
    float2 xv = reinterpret_cast<const float2*>(x)[warp * 32 + lane];
    g_xh[warp * 32 + lane] = __floats2half2_rn(xv.x, xv.y);
    int l2 = lane * 2;
    float s10 = xv.x * v00[l2] + xv.y * v00[l2 + 1];
    float s20 = xv.x * v01[l2] + xv.y * v01[l2 + 1];
    float s11 = xv.x * v10[l2] + xv.y * v10[l2 + 1];
    float s21 = xv.x * v11[l2] + xv.y * v11[l2 + 1];
    #pragma unroll
    for (int o = 16; o; o >>= 1) {
        s10 += __shfl_xor_sync(0xffffffffu, s10, o);
        s20 += __shfl_xor_sync(0xffffffffu, s20, o);
        s11 += __shfl_xor_sync(0xffffffffu, s11, o);
        s21 += __shfl_xor_sync(0xffffffffu, s21, o);
    }
    if (lane == 0) {
        g_s1[warp] = make_float2(s10, s11);
        g_s2[warp] = make_float2(s20, s21);
    }
}

// Single edge-parallel pass: slot via atomic histogram, both head weights in
// fp16, one 8B record into the L2-resident ELL row.
__global__ void k_build(const int* __restrict__ row,
                        const int* __restrict__ col, int E) {
    int i = blockIdx.x * blockDim.x + threadIdx.x;
    if (i >= E) return;
    int r = row[i], c = col[i];
    int slot = atomicAdd(&g_cnt[r], 1);
    if (slot < CAP) {
        float2 s1 = g_s1[r];
        float2 s2 = g_s2[c];
        float sc0 = s1.x + s2.x;
        float sc1 = s1.y + s2.y;
        float w0 = __expf(sc0 > 0.f ? sc0 : ALPHA * sc0);
        float w1 = __expf(sc1 > 0.f ? sc1 : ALPHA * sc1);
        __half2 wh = __floats2half2_rn(w0, w1);
        unsigned wbits = *reinterpret_cast<unsigned*>(&wh);
        g_ell[r * CAP + slot] = ((unsigned long long)(unsigned)c << 32) | wbits;
    }
}

// One warp per node: records consumed in aligned pairs (one LDG.128 covers
// two edges; two independent x gathers in flight). Resets g_cnt for replay.
__global__ void k_aggregate(float* __restrict__ out, int n) {
    int warp = (blockIdx.x * blockDim.x + threadIdx.x) >> 5;
    int lane = threadIdx.x & 31;
    if (warp >= n) return;
    int deg = g_cnt[warp];
    if (lane == 0) g_cnt[warp] = 0;
    deg = min(deg, CAP);
    const unsigned long long* __restrict__ erow = g_ell + warp * CAP;
    float a00 = 0.f, a01 = 0.f, a10 = 0.f, a11 = 0.f;
    float rs0 = 0.f, rs1 = 0.f;

    int j = 0;
    for (; j + 1 < deg; j += 2) {      // base is 16B-aligned (CAP*8 = 384B)
        uint4 q = *reinterpret_cast<const uint4*>(erow + j);
        int c0 = (int)q.y, c1 = (int)q.w;
        float2 w0 = __half22float2(*reinterpret_cast<__half2*>(&q.x));
        float2 w1 = __half22float2(*reinterpret_cast<__half2*>(&q.z));
        float2 x0 = __half22float2(g_xh[c0 * 32 + lane]);
        float2 x1 = __half22float2(g_xh[c1 * 32 + lane]);
        a00 += w0.x * x0.x; a01 += w0.x * x0.y;
        a10 += w0.y * x0.x; a11 += w0.y * x0.y;
        rs0 += w0.x; rs1 += w0.y;
        a00 += w1.x * x1.x; a01 += w1.x * x1.y;
        a10 += w1.y * x1.x; a11 += w1.y * x1.y;
        rs0 += w1.x; rs1 += w1.y;
    }
    if (j < deg) {                     // tail
        unsigned long long r = erow[j];
        unsigned lo = (unsigned)r;
        int c = (int)(r >> 32);
        float2 w = __half22float2(*reinterpret_cast<__half2*>(&lo));
        float2 xf = __half22float2(g_xh[c * 32 + lane]);
        a00 += w.x * xf.x; a01 += w.x * xf.y;
        a10 += w.y * xf.x; a11 += w.y * xf.y;
        rs0 += w.x; rs1 += w.y;
    }

    float i0 = 0.5f / rs0, i1 = 0.5f / rs1;
    float2 o;
    o.x = a00 * i0 + a10 * i1;
    o.y = a01 * i0 + a11 * i1;
    reinterpret_cast<float2*>(out)[warp * 32 + lane] = o;
}

extern "C" void kernel_launch(void* const* d_in, const int* in_sizes, int n_in,
                              void* d_out, int out_size) {
    const float* x  = (const float*)d_in[0];
    const int*   ei = (const int*)d_in[1];
    const float* W  = (const float*)d_in[2];
    const float* a  = (const float*)d_in[3];
    float* out = (float*)d_out;

    int n = in_sizes[0] / D;
    int E = in_sizes[1] / 2;
    const int* row = ei;
    const int* col = ei + E;

    const int T = 256;
    int nbE = (E + T - 1) / T;
    int nbW = (n * 32 + T - 1) / T;   // one warp per node

    k_precompute<<<nbW, T>>>(x, W, a, n);
    k_build<<<nbE, T>>>(row, col, E);
    k_aggregate<<<nbW, T>>>(out, n);
}

// round 7
// speedup vs baseline: 1.8690x; 1.8690x over previous
#include <cuda_runtime.h>
#include <cuda_fp16.h>

#define D 64
#define ALPHA 0.2f
#define MAX_N 131072
#define MAX_E 2200000
#define SCAN_B 512

// Static scratch (BSS zero-init; k_scan_apply re-zeroes g_cnt every run so
// graph replays always see a clean histogram).
__device__ int     g_cnt[MAX_N];
__device__ int     g_rowptr[MAX_N + 1];
__device__ int     g_blocksum[SCAN_B];
__device__ int     g_slot[MAX_E];     // per-edge within-row slot from hist
__device__ __align__(16) unsigned long long g_rec[MAX_E]; // (col<<32)|half2(w0,w1)
__device__ float4  g_s[MAX_N];        // packed per-node scores (s1.x,s1.y,s2.x,s2.y)
__device__ __half2 g_xh[MAX_N * 32];  // fp16 copy of x, 2 feats per lane

// Fused: blocks [0,nbE) do the edge histogram (slot assignment); blocks
// [nbE, nbE+nbW) do per-node score precompute + fp16 conversion of x.
__global__ void k_pre_hist(const float* __restrict__ x,
                           const float* __restrict__ W,
                           const float* __restrict__ a,
                           const int* __restrict__ row,
                           int n, int E, int nbE) {
    int t = threadIdx.x;
    if ((int)blockIdx.x < nbE) {
        int i = blockIdx.x * blockDim.x + t;
        if (i < E) g_slot[i] = atomicAdd(&g_cnt[row[i]], 1);
        return;
    }
    // Fused W*a per-feature vectors, stored as float2 per lane-pair.
    __shared__ float2 v00[32], v01[32], v10[32], v11[32];
    if (t < 32) {
        int l2 = t * 2;
        float w0a = W[l2], w0b = W[l2 + 1];
        float w1a = W[64 + l2], w1b = W[64 + l2 + 1];
        v00[t] = make_float2(w0a * a[l2],        w0b * a[l2 + 1]);
        v01[t] = make_float2(w0a * a[64 + l2],   w0b * a[64 + l2 + 1]);
        v10[t] = make_float2(w1a * a[128 + l2],  w1b * a[128 + l2 + 1]);
        v11[t] = make_float2(w1a * a[192 + l2],  w1b * a[192 + l2 + 1]);
    }
    __syncthreads();
    int b = blockIdx.x - nbE;
    int warp = (b * blockDim.x + t) >> 5;
    int lane = t & 31;
    if (warp >= n) return;
    float2 xv = reinterpret_cast<const float2*>(x)[warp * 32 + lane];
    g_xh[warp * 32 + lane] = __floats2half2_rn(xv.x, xv.y);
    float2 c00 = v00[lane], c01 = v01[lane], c10 = v10[lane], c11 = v11[lane];
    float s10 = xv.x * c00.x + xv.y * c00.y;
    float s20 = xv.x * c01.x + xv.y * c01.y;
    float s11 = xv.x * c10.x + xv.y * c10.y;
    float s21 = xv.x * c11.x + xv.y * c11.y;
    #pragma unroll
    for (int o = 16; o; o >>= 1) {
        s10 += __shfl_xor_sync(0xffffffffu, s10, o);
        s20 += __shfl_xor_sync(0xffffffffu, s20, o);
        s11 += __shfl_xor_sync(0xffffffffu, s11, o);
        s21 += __shfl_xor_sync(0xffffffffu, s21, o);
    }
    if (lane == 0) g_s[warp] = make_float4(s10, s11, s20, s21);
}

// Block-local exclusive scan of g_cnt -> g_rowptr (local) + block totals.
__global__ void k_scan1(int n) {
    __shared__ int sh[SCAN_B];
    int t = threadIdx.x;
    int i = blockIdx.x * SCAN_B + t;
    int v = (i < n) ? g_cnt[i] : 0;
    sh[t] = v;
    __syncthreads();
    #pragma unroll
    for (int o = 1; o < SCAN_B; o <<= 1) {
        int tmp = (t >= o) ? sh[t - o] : 0;
        __syncthreads();
        sh[t] += tmp;
        __syncthreads();
    }
    if (i < n) g_rowptr[i] = sh[t] - v;
    if (t == SCAN_B - 1) g_blocksum[blockIdx.x] = sh[t];
}

// Every block redundantly scans the (<=512) block sums in smem, adds its own
// base to the local prefixes, re-zeroes g_cnt, and caps rowptr[n]=E.
__global__ void k_scan_apply(int n, int E, int nb) {
    __shared__ int sh[SCAN_B];
    int t = threadIdx.x;
    sh[t] = (t < nb) ? g_blocksum[t] : 0;
    __syncthreads();
    #pragma unroll
    for (int o = 1; o < SCAN_B; o <<= 1) {
        int tmp = (t >= o) ? sh[t - o] : 0;
        __syncthreads();
        sh[t] += tmp;
        __syncthreads();
    }
    int base = (blockIdx.x == 0) ? 0 : sh[blockIdx.x - 1];
    int i = blockIdx.x * SCAN_B + t;
    if (i < n) {
        g_rowptr[i] += base;
        g_cnt[i] = 0;
    }
    if (i == n) g_rowptr[n] = E;
}

// Edge-parallel CSR fill (atomic-free). Packed g_s: one 16B gather per side
// (one 32B sector each) instead of two separate s1/s2 arrays.
__global__ void k_scatter(const int* __restrict__ row,
                          const int* __restrict__ col, int E) {
    int i = blockIdx.x * blockDim.x + threadIdx.x;
    if (i >= E) return;
    int r = row[i], c = col[i];
    int pos = g_rowptr[r] + g_slot[i];
    float4 sr = g_s[r];   // (s1r.x, s1r.y, -, -)
    float4 sc = g_s[c];   // (-, -, s2c.x, s2c.y)
    float sc0 = sr.x + sc.z;
    float sc1 = sr.y + sc.w;
    float w0 = __expf(sc0 > 0.f ? sc0 : ALPHA * sc0);
    float w1 = __expf(sc1 > 0.f ? sc1 : ALPHA * sc1);
    __half2 wh = __floats2half2_rn(w0, w1);
    unsigned wbits = *reinterpret_cast<unsigned*>(&wh);
    g_rec[pos] = ((unsigned long long)(unsigned)c << 32) | wbits;
}

// One warp per node. Records consumed 4 at a time (two LDG.128) -> four
// independent x gathers in flight per iteration.
__global__ void k_aggregate(float* __restrict__ out, int n) {
    int warp = (blockIdx.x * blockDim.x + threadIdx.x) >> 5;
    int lane = threadIdx.x & 31;
    if (warp >= n) return;
    int beg = g_rowptr[warp];
    int end = g_rowptr[warp + 1];
    float a00 = 0.f, a01 = 0.f, a10 = 0.f, a11 = 0.f;
    float rs0 = 0.f, rs1 = 0.f;

    int e = beg;
    // head: align e to even (16B) boundary
    if (e < end && (e & 1)) {
        unsigned long long r = g_rec[e];
        unsigned lo = (unsigned)r;
        int c = (int)(r >> 32);
        float2 w = __half22float2(*reinterpret_cast<__half2*>(&lo));
        float2 xf = __half22float2(g_xh[c * 32 + lane]);
        a00 += w.x * xf.x; a01 += w.x * xf.y;
        a10 += w.y * xf.x; a11 += w.y * xf.y;
        rs0 += w.x; rs1 += w.y;
        e++;
    }
    // main: 4 edges per iteration
    for (; e + 3 < end; e += 4) {
        uint4 qa = *reinterpret_cast<const uint4*>(&g_rec[e]);
        uint4 qb = *reinterpret_cast<const uint4*>(&g_rec[e + 2]);
        int c0 = (int)qa.y, c1 = (int)qa.w;
        int c2 = (int)qb.y, c3 = (int)qb.w;
        float2 x0 = __half22float2(g_xh[c0 * 32 + lane]);
        float2 x1 = __half22float2(g_xh[c1 * 32 + lane]);
        float2 x2 = __half22float2(g_xh[c2 * 32 + lane]);
        float2 x3 = __half22float2(g_xh[c3 * 32 + lane]);
        float2 w0 = __half22float2(*reinterpret_cast<__half2*>(&qa.x));
        float2 w1 = __half22float2(*reinterpret_cast<__half2*>(&qa.z));
        float2 w2 = __half22float2(*reinterpret_cast<__half2*>(&qb.x));
        float2 w3 = __half22float2(*reinterpret_cast<__half2*>(&qb.z));
        a00 += w0.x * x0.x; a01 += w0.x * x0.y;
        a10 += w0.y * x0.x; a11 += w0.y * x0.y;
        rs0 += w0.x; rs1 += w0.y;
        a00 += w1.x * x1.x; a01 += w1.x * x1.y;
        a10 += w1.y * x1.x; a11 += w1.y * x1.y;
        rs0 += w1.x; rs1 += w1.y;
        a00 += w2.x * x2.x; a01 += w2.x * x2.y;
        a10 += w2.y * x2.x; a11 += w2.y * x2.y;
        rs0 += w2.x; rs1 += w2.y;
        a00 += w3.x * x3.x; a01 += w3.x * x3.y;
        a10 += w3.y * x3.x; a11 += w3.y * x3.y;
        rs0 += w3.x; rs1 += w3.y;
    }
    // tail
    for (; e < end; e++) {
        unsigned long long r = g_rec[e];
        unsigned lo = (unsigned)r;
        int c = (int)(r >> 32);
        float2 w = __half22float2(*reinterpret_cast<__half2*>(&lo));
        float2 xf = __half22float2(g_xh[c * 32 + lane]);
        a00 += w.x * xf.x; a01 += w.x * xf.y;
        a10 += w.y * xf.x; a11 += w.y * xf.y;
        rs0 += w.x; rs1 += w.y;
    }

    float i0 = 0.5f / rs0, i1 = 0.5f / rs1;
    float2 o;
    o.x = a00 * i0 + a10 * i1;
    o.y = a01 * i0 + a11 * i1;
    reinterpret_cast<float2*>(out)[warp * 32 + lane] = o;
}

extern "C" void kernel_launch(void* const* d_in, const int* in_sizes, int n_in,
                              void* d_out, int out_size) {
    const float* x  = (const float*)d_in[0];
    const int*   ei = (const int*)d_in[1];
    const float* W  = (const float*)d_in[2];
    const float* a  = (const float*)d_in[3];
    float* out = (float*)d_out;

    int n = in_sizes[0] / D;
    int E = in_sizes[1] / 2;
    const int* row = ei;
    const int* col = ei + E;

    const int T = 256;
    int nbE = (E + T - 1) / T;
    int nbW = (n * 32 + T - 1) / T;          // one warp per node
    int nbS = (n + SCAN_B - 1) / SCAN_B;     // must be <= SCAN_B

    k_pre_hist<<<nbE + nbW, T>>>(x, W, a, row, n, E, nbE);
    k_scan1<<<nbS, SCAN_B>>>(n);
    k_scan_apply<<<(n + SCAN_B) / SCAN_B, SCAN_B>>>(n, E, nbS);
    k_scatter<<<nbE, T>>>(row, col, E);
    k_aggregate<<<nbW, T>>>(out, n);
}